// round 4
// baseline (speedup 1.0000x reference)
#include <cuda_runtime.h>
#include <cuda_bf16.h>
#include <math.h>

// Problem constants
#define BB 2
#define II 768
#define CA 768
#define CS 384
#define CZ 128
#define HH 16
#define DD 48
#define HC 768
#define ROWS (BB*II)          // 1536
#define EPS 1e-5f

// ---------------- device scratch (no allocations allowed) ----------------
__device__ float g_aln  [ROWS*CA];
__device__ float g_sln  [ROWS*CS];
__device__ float g_t1   [ROWS*CA];
__device__ float g_t2   [ROWS*CA];
__device__ float g_a2   [ROWS*CA];
__device__ float g_q    [ROWS*HC];
__device__ float g_k    [ROWS*HC];
__device__ float g_v    [ROWS*HC];
__device__ float g_gbuf [ROWS*HC];
__device__ float g_gate [ROWS*CA];
__device__ float g_scores[(size_t)BB*HH*II*II];   // [b][h][i][j]  ~75.5 MB
__device__ float g_o    [ROWS*HC];
__device__ float g_out0 [ROWS*CA];

// ---------------- LayerNorm over rows ----------------
__global__ void ln_kernel(const float* __restrict__ x,
                          const float* __restrict__ w,
                          const float* __restrict__ b,
                          float* __restrict__ y, int C)
{
    int row = blockIdx.x;
    const float* xr = x + (size_t)row * C;
    float s1 = 0.f, s2 = 0.f;
    for (int c = threadIdx.x; c < C; c += blockDim.x) {
        float v = xr[c]; s1 += v; s2 += v * v;
    }
    __shared__ float red[64];
    #pragma unroll
    for (int o = 16; o; o >>= 1) {
        s1 += __shfl_xor_sync(0xffffffffu, s1, o);
        s2 += __shfl_xor_sync(0xffffffffu, s2, o);
    }
    int wid = threadIdx.x >> 5, lid = threadIdx.x & 31;
    if (lid == 0) { red[wid] = s1; red[wid + 32] = s2; }
    __syncthreads();
    if (wid == 0) {
        s1 = (lid < (blockDim.x >> 5)) ? red[lid] : 0.f;
        s2 = (lid < (blockDim.x >> 5)) ? red[lid + 32] : 0.f;
        #pragma unroll
        for (int o = 16; o; o >>= 1) {
            s1 += __shfl_xor_sync(0xffffffffu, s1, o);
            s2 += __shfl_xor_sync(0xffffffffu, s2, o);
        }
        if (lid == 0) { red[0] = s1; red[1] = s2; }
    }
    __syncthreads();
    float mean = red[0] / C;
    float var  = red[1] / C - mean * mean;
    float rs   = rsqrtf(var + EPS);
    float* yr = y + (size_t)row * C;
    for (int c = threadIdx.x; c < C; c += blockDim.x) {
        float v = (xr[c] - mean) * rs;
        if (w) v = v * w[c] + b[c];
        yr[c] = v;
    }
}

// ---------------- generic fp32 GEMM: C = A[M,K] @ W[K,N] (+bias) (sigmoid) ----------------
// 64x64 tile, BK=16, 256 threads, 4x4 microtile
__global__ void gemm_kernel(const float* __restrict__ A,
                            const float* __restrict__ W,
                            const float* __restrict__ bias,
                            float* __restrict__ C,
                            int M, int N, int K, int sig)
{
    __shared__ float As[16][65];
    __shared__ float Bs[16][64];
    int t = threadIdx.x;
    int m0 = blockIdx.y * 64, n0 = blockIdx.x * 64;
    int tx = t & 15, ty = t >> 4;
    float acc[4][4] = {};
    for (int k0 = 0; k0 < K; k0 += 16) {
        {   // A tile 64x16 -> transposed
            int r = t >> 2, c4 = (t & 3) * 4;
            float4 a = *(const float4*)&A[(size_t)(m0 + r) * K + k0 + c4];
            As[c4 + 0][r] = a.x; As[c4 + 1][r] = a.y;
            As[c4 + 2][r] = a.z; As[c4 + 3][r] = a.w;
        }
        {   // W tile 16x64
            int r = t >> 4, c4 = (t & 15) * 4;
            *(float4*)&Bs[r][c4] = *(const float4*)&W[(size_t)(k0 + r) * N + n0 + c4];
        }
        __syncthreads();
        #pragma unroll
        for (int kk = 0; kk < 16; kk++) {
            float a[4], b[4];
            #pragma unroll
            for (int u = 0; u < 4; u++) a[u] = As[kk][ty * 4 + u];
            float4 b4 = *(float4*)&Bs[kk][tx * 4];
            b[0] = b4.x; b[1] = b4.y; b[2] = b4.z; b[3] = b4.w;
            #pragma unroll
            for (int i = 0; i < 4; i++)
                #pragma unroll
                for (int j = 0; j < 4; j++)
                    acc[i][j] += a[i] * b[j];
        }
        __syncthreads();
    }
    #pragma unroll
    for (int i = 0; i < 4; i++) {
        int m = m0 + ty * 4 + i;
        #pragma unroll
        for (int j = 0; j < 4; j++) {
            int n = n0 + tx * 4 + j;
            float c = acc[i][j];
            if (bias) c += bias[n];
            if (sig) c = 1.f / (1.f + expf(-c));
            C[(size_t)m * N + n] = c;
        }
    }
}

// ---------------- elementwise ----------------
__global__ void adaln_ew_kernel(const float* __restrict__ t1,
                                const float* __restrict__ t2,
                                const float* __restrict__ aln,
                                float* __restrict__ a2, int n)
{
    int i = blockIdx.x * blockDim.x + threadIdx.x;
    if (i < n) {
        float s = 1.f / (1.f + expf(-t1[i]));
        a2[i] = s * aln[i] + t2[i];
    }
}

__global__ void final_ew_kernel(const float* __restrict__ gate,
                                const float* __restrict__ out0,
                                float* __restrict__ out, int n)
{
    int i = blockIdx.x * blockDim.x + threadIdx.x;
    if (i < n) out[i] = gate[i] * out0[i];
}

// ---------------- pair bias: scores[b][h][i][j] = LN(z_ij)@Wb + beta ----------------
__global__ void pairbias_kernel(const float* __restrict__ z,
                                const float* __restrict__ beta,
                                const float* __restrict__ lnb_w,
                                const float* __restrict__ lnb_b,
                                const float* __restrict__ Wb,
                                float* __restrict__ scores)
{
    __shared__ float4 wb2v[16][32];          // [h][c/4] combined w_c*Wb[c,h]
    __shared__ float colsum[16], consth[16];
    float* wb2 = (float*)wb2v;
    int t = threadIdx.x;                     // 256 threads
    for (int e = t; e < 16 * 128; e += 256) {
        int h = e >> 7, c = e & 127;
        wb2[h * 128 + c] = lnb_w[c] * Wb[c * 16 + h];
    }
    __syncthreads();
    if (t < 16) {
        float cs = 0.f, ch = 0.f;
        for (int c = 0; c < 128; c++) {
            cs += wb2[t * 128 + c];
            ch += lnb_b[c] * Wb[c * 16 + t];
        }
        colsum[t] = cs; consth[t] = ch;
    }
    __syncthreads();

    int bi = blockIdx.x;                     // b*768 + i
    int b = bi / II, i = bi % II;
    int warp = t >> 5, lane = t & 31;

    for (int j = warp; j < II; j += 8) {
        size_t zoff = ((size_t)bi * II + j) * CZ;
        float4 z4 = *(const float4*)&z[zoff + lane * 4];
        float s1 = z4.x + z4.y + z4.z + z4.w;
        float s2 = z4.x * z4.x + z4.y * z4.y + z4.z * z4.z + z4.w * z4.w;
        #pragma unroll
        for (int o = 16; o; o >>= 1) {
            s1 += __shfl_xor_sync(0xffffffffu, s1, o);
            s2 += __shfl_xor_sync(0xffffffffu, s2, o);
        }
        float mean = s1 * (1.f / 128.f);
        float var  = s2 * (1.f / 128.f) - mean * mean;
        float rs   = rsqrtf(var + EPS);
        float myv = 0.f;
        #pragma unroll
        for (int h = 0; h < 16; h++) {
            float4 w4 = wb2v[h][lane];
            float p = z4.x * w4.x + z4.y * w4.y + z4.z * w4.z + z4.w * w4.w;
            #pragma unroll
            for (int o = 16; o; o >>= 1) p += __shfl_xor_sync(0xffffffffu, p, o);
            if (lane == h) myv = rs * (p - mean * colsum[h]) + consth[h];
        }
        if (lane < 16) {
            float val = myv + beta[((size_t)bi * II + j) * HH + lane];
            scores[(((size_t)b * HH + lane) * II + i) * II + j] = val;
        }
    }
}

// ---------------- scores += q.k / sqrt(D) ----------------
__global__ void qk_kernel(const float* __restrict__ q,
                          const float* __restrict__ k,
                          float* __restrict__ scores)
{
    __shared__ float qs[32][49], ks[32][49];
    int bh = blockIdx.z;
    int b = bh >> 4, h = bh & 15;
    int i0 = blockIdx.y * 32, j0 = blockIdx.x * 32;
    int t = threadIdx.x;                     // 256
    for (int e = t; e < 32 * 48; e += 256) {
        int r = e / 48, d = e % 48;
        qs[r][d] = q[(((size_t)b * II + i0 + r) * HH + h) * DD + d];
        ks[r][d] = k[(((size_t)b * II + j0 + r) * HH + h) * DD + d];
    }
    __syncthreads();
    int tx = t & 15, ty = t >> 4;
    float acc[2][2] = {};
    #pragma unroll 8
    for (int d = 0; d < 48; d++) {
        float a0 = qs[ty * 2][d],     a1 = qs[ty * 2 + 1][d];
        float b0 = ks[tx * 2][d],     b1 = ks[tx * 2 + 1][d];
        acc[0][0] += a0 * b0; acc[0][1] += a0 * b1;
        acc[1][0] += a1 * b0; acc[1][1] += a1 * b1;
    }
    const float sc = rsqrtf(48.f);
    #pragma unroll
    for (int ii = 0; ii < 2; ii++)
        #pragma unroll
        for (int jj = 0; jj < 2; jj++) {
            size_t idx = (((size_t)bh * II) + i0 + ty * 2 + ii) * II + j0 + tx * 2 + jj;
            scores[idx] += acc[ii][jj] * sc;
        }
}

// ---------------- softmax over j + AV + gate: o[b,i,h,d] ----------------
// grid: x = I/16 (i tile), y = B*H.  block = 192 threads.
__global__ void softmax_av_kernel(const float* __restrict__ scores,
                                  const float* __restrict__ v,
                                  const float* __restrict__ gbuf,
                                  float* __restrict__ o)
{
    __shared__ float p[16][II];              // 48KB
    __shared__ float vs[32][48];             // 6KB
    int bh = blockIdx.y, b = bh >> 4, h = bh & 15;
    int ibase = blockIdx.x * 16;
    int t = threadIdx.x, warp = t >> 5, lane = t & 31;

    // phase 1: softmax of 16 rows
    for (int r = warp; r < 16; r += 6) {
        const float* srow = &scores[(((size_t)bh * II) + ibase + r) * II];
        float mx = -1e30f;
        for (int j = lane; j < II; j += 32) {
            float s = srow[j]; p[r][j] = s; mx = fmaxf(mx, s);
        }
        #pragma unroll
        for (int off = 16; off; off >>= 1) mx = fmaxf(mx, __shfl_xor_sync(0xffffffffu, mx, off));
        float sum = 0.f;
        for (int j = lane; j < II; j += 32) {
            float e = expf(p[r][j] - mx); p[r][j] = e; sum += e;
        }
        #pragma unroll
        for (int off = 16; off; off >>= 1) sum += __shfl_xor_sync(0xffffffffu, sum, off);
        float inv = 1.f / sum;
        for (int j = lane; j < II; j += 32) p[r][j] *= inv;
    }
    __syncthreads();

    // phase 2: o[i,d] = sum_j p[i][j] * v[j][d]
    int ia = t / 24, d0 = t % 24;            // ia 0..7, d0 0..23
    float acc[2][2] = {};
    for (int jt = 0; jt < II / 32; jt++) {
        for (int e = t; e < 32 * 48; e += 192) {
            int jj = e / 48, d = e % 48;
            vs[jj][d] = v[(((size_t)b * II + jt * 32 + jj) * HH + h) * DD + d];
        }
        __syncthreads();
        #pragma unroll 8
        for (int jj = 0; jj < 32; jj++) {
            float p0 = p[ia][jt * 32 + jj];
            float p1 = p[ia + 8][jt * 32 + jj];
            float v0 = vs[jj][d0];
            float v1 = vs[jj][d0 + 24];
            acc[0][0] += p0 * v0; acc[0][1] += p0 * v1;
            acc[1][0] += p1 * v0; acc[1][1] += p1 * v1;
        }
        __syncthreads();
    }
    #pragma unroll
    for (int u = 0; u < 2; u++)
        #pragma unroll
        for (int w2 = 0; w2 < 2; w2++) {
            int i = ibase + ia + u * 8;
            int d = d0 + w2 * 24;
            size_t gi = (((size_t)b * II + i) * HH + h) * DD + d;
            float g = 1.f / (1.f + expf(-gbuf[gi]));
            o[gi] = acc[u][w2] * g;
        }
}

// ---------------- host launch ----------------
static float* sym(const void* s) {
    void* p = nullptr;
    cudaGetSymbolAddress(&p, s);
    return (float*)p;
}

extern "C" void kernel_launch(void* const* d_in, const int* in_sizes, int n_in,
                              void* d_out, int out_size)
{
    const float* a_i      = (const float*)d_in[0];
    const float* s_i      = (const float*)d_in[1];
    const float* z_ij     = (const float*)d_in[2];
    const float* beta_ij  = (const float*)d_in[3];
    const float* lns_w    = (const float*)d_in[4];
    const float* lns_b    = (const float*)d_in[5];
    const float* Ws       = (const float*)d_in[6];
    const float* bs       = (const float*)d_in[7];
    const float* Wnb      = (const float*)d_in[8];
    const float* Wq       = (const float*)d_in[9];
    const float* bq       = (const float*)d_in[10];
    const float* Wk       = (const float*)d_in[11];
    const float* Wv       = (const float*)d_in[12];
    const float* lnb_w    = (const float*)d_in[13];
    const float* lnb_b    = (const float*)d_in[14];
    const float* Wb       = (const float*)d_in[15];
    const float* Wg       = (const float*)d_in[16];
    const float* Wo       = (const float*)d_in[17];
    const float* Ws_out   = (const float*)d_in[18];
    const float* bs_out   = (const float*)d_in[19];
    float* out = (float*)d_out;

    float* p_aln  = sym(g_aln);
    float* p_sln  = sym(g_sln);
    float* p_t1   = sym(g_t1);
    float* p_t2   = sym(g_t2);
    float* p_a2   = sym(g_a2);
    float* p_q    = sym(g_q);
    float* p_k    = sym(g_k);
    float* p_v    = sym(g_v);
    float* p_g    = sym(g_gbuf);
    float* p_gate = sym(g_gate);
    float* p_sc   = sym(g_scores);
    float* p_o    = sym(g_o);
    float* p_out0 = sym(g_out0);

    const int NEL = ROWS * CA;

    // 1-2: LayerNorms
    ln_kernel<<<ROWS, 256>>>(a_i, nullptr, nullptr, p_aln, CA);
    ln_kernel<<<ROWS, 256>>>(s_i, lns_w, lns_b, p_sln, CS);

    // 3-5: AdaLN
    {
        dim3 g(CA / 64, ROWS / 64);
        gemm_kernel<<<g, 256>>>(p_sln, Ws,  bs,      p_t1, ROWS, CA, CS, 0);
        gemm_kernel<<<g, 256>>>(p_sln, Wnb, nullptr, p_t2, ROWS, CA, CS, 0);
    }
    adaln_ew_kernel<<<(NEL + 255) / 256, 256>>>(p_t1, p_t2, p_aln, p_a2, NEL);

    // 6-9: projections
    {
        dim3 g(HC / 64, ROWS / 64);
        gemm_kernel<<<g, 256>>>(p_a2, Wq, bq,      p_q, ROWS, HC, CA, 0);
        gemm_kernel<<<g, 256>>>(p_a2, Wk, nullptr, p_k, ROWS, HC, CA, 0);
        gemm_kernel<<<g, 256>>>(p_a2, Wv, nullptr, p_v, ROWS, HC, CA, 0);
        gemm_kernel<<<g, 256>>>(p_a2, Wg, nullptr, p_g, ROWS, HC, CA, 0);
    }

    // 10: output gate from raw s_i
    {
        dim3 g(CA / 64, ROWS / 64);
        gemm_kernel<<<g, 256>>>(s_i, Ws_out, bs_out, p_gate, ROWS, CA, CS, 1);
    }

    // 11: pair bias (writes scores)
    pairbias_kernel<<<ROWS, 256>>>(z_ij, beta_ij, lnb_w, lnb_b, Wb, p_sc);

    // 12: scores += qk/sqrt(D)
    {
        dim3 g(II / 32, II / 32, BB * HH);
        qk_kernel<<<g, 256>>>(p_q, p_k, p_sc);
    }

    // 13: softmax + AV + gate
    {
        dim3 g(II / 16, BB * HH);
        softmax_av_kernel<<<g, 192>>>(p_sc, p_v, p_g, p_o);
    }

    // 14: out0 = o @ Wo
    {
        dim3 g(CA / 64, ROWS / 64);
        gemm_kernel<<<g, 256>>>(p_o, Wo, nullptr, p_out0, ROWS, CA, HC, 0);
    }

    // 15: final gating
    final_ew_kernel<<<(NEL + 255) / 256, 256>>>(p_gate, p_out0, out, NEL);
}

// round 5
// speedup vs baseline: 2.6556x; 2.6556x over previous
#include <cuda_runtime.h>
#include <cuda_bf16.h>
#include <math.h>

// Problem constants
#define BB 2
#define II 768
#define CA 768
#define CS 384
#define CZ 128
#define HH 16
#define DD 48
#define HC 768
#define ROWS (BB*II)          // 1536
#define EPS 1e-5f

// ---------------- device scratch (no allocations allowed) ----------------
__device__ float g_aln  [ROWS*CA];
__device__ float g_sln  [ROWS*CS];
__device__ float g_t1   [ROWS*CA];
__device__ float g_t2   [ROWS*CA];
__device__ float g_a2   [ROWS*CA];
__device__ float g_q    [ROWS*HC];
__device__ float g_k    [ROWS*HC];
__device__ float g_v    [ROWS*HC];
__device__ float g_gbuf [ROWS*HC];
__device__ float g_gate [ROWS*CA];
__device__ float g_scores[(size_t)BB*HH*II*II];   // [b][h][i][j]  ~75.5 MB
__device__ float g_o    [ROWS*HC];

// ---------------- LayerNorm over rows ----------------
__global__ void ln_kernel(const float* __restrict__ x,
                          const float* __restrict__ w,
                          const float* __restrict__ b,
                          float* __restrict__ y, int C)
{
    int row = blockIdx.x;
    const float* xr = x + (size_t)row * C;
    float s1 = 0.f, s2 = 0.f;
    for (int c = threadIdx.x; c < C; c += blockDim.x) {
        float v = xr[c]; s1 += v; s2 += v * v;
    }
    __shared__ float red[64];
    #pragma unroll
    for (int o = 16; o; o >>= 1) {
        s1 += __shfl_xor_sync(0xffffffffu, s1, o);
        s2 += __shfl_xor_sync(0xffffffffu, s2, o);
    }
    int wid = threadIdx.x >> 5, lid = threadIdx.x & 31;
    if (lid == 0) { red[wid] = s1; red[wid + 32] = s2; }
    __syncthreads();
    if (wid == 0) {
        s1 = (lid < (blockDim.x >> 5)) ? red[lid] : 0.f;
        s2 = (lid < (blockDim.x >> 5)) ? red[lid + 32] : 0.f;
        #pragma unroll
        for (int o = 16; o; o >>= 1) {
            s1 += __shfl_xor_sync(0xffffffffu, s1, o);
            s2 += __shfl_xor_sync(0xffffffffu, s2, o);
        }
        if (lid == 0) { red[0] = s1; red[1] = s2; }
    }
    __syncthreads();
    float mean = red[0] / C;
    float var  = red[1] / C - mean * mean;
    float rs   = rsqrtf(var + EPS);
    float* yr = y + (size_t)row * C;
    for (int c = threadIdx.x; c < C; c += blockDim.x) {
        float v = (xr[c] - mean) * rs;
        if (w) v = v * w[c] + b[c];
        yr[c] = v;
    }
}

// ---------------- fp32 GEMM: C = A[M,K] @ W[K,N] (+bias)(sig)(*mulp) ------
// 128x64 tile, BK=16, 256 threads, 8x4 microtile, double-buffered smem.
__global__ void __launch_bounds__(256)
gemm_kernel(const float* __restrict__ A, const float* __restrict__ W,
            const float* __restrict__ bias, const float* __restrict__ mulp,
            float* __restrict__ C, int M, int N, int K, int sig)
{
    __shared__ __align__(16) float As[2][16][132];
    __shared__ __align__(16) float Bs[2][16][64];
    int t = threadIdx.x;
    int m0 = blockIdx.y * 128, n0 = blockIdx.x * 64;
    int ar = t >> 1, ak = (t & 1) * 8;
    int br = t >> 4, bc = (t & 15) * 4;
    const float* Ap = A + (size_t)(m0 + ar) * K + ak;
    const float* Wp = W + (size_t)br * N + n0 + bc;

    float acc[8][4] = {};
    {
        float4 a0 = *(const float4*)Ap;
        float4 a1 = *(const float4*)(Ap + 4);
        As[0][ak+0][ar]=a0.x; As[0][ak+1][ar]=a0.y; As[0][ak+2][ar]=a0.z; As[0][ak+3][ar]=a0.w;
        As[0][ak+4][ar]=a1.x; As[0][ak+5][ar]=a1.y; As[0][ak+6][ar]=a1.z; As[0][ak+7][ar]=a1.w;
        *(float4*)&Bs[0][br][bc] = *(const float4*)Wp;
    }
    __syncthreads();
    int nt = K >> 4;
    int ty = t >> 4, tx = t & 15;
    for (int kt = 0; kt < nt; kt++) {
        int cur = kt & 1;
        float4 a0n, a1n, bn;
        bool pref = (kt + 1 < nt);
        if (pref) {
            const float* Ap2 = Ap + (kt + 1) * 16;
            a0n = *(const float4*)Ap2;
            a1n = *(const float4*)(Ap2 + 4);
            bn  = *(const float4*)(Wp + (size_t)(kt + 1) * 16 * N);
        }
        #pragma unroll
        for (int kk = 0; kk < 16; kk++) {
            float4 av0 = *(const float4*)&As[cur][kk][ty*8];
            float4 av1 = *(const float4*)&As[cur][kk][ty*8+4];
            float4 bv  = *(const float4*)&Bs[cur][kk][tx*4];
            float a[8] = {av0.x,av0.y,av0.z,av0.w,av1.x,av1.y,av1.z,av1.w};
            float bb[4] = {bv.x,bv.y,bv.z,bv.w};
            #pragma unroll
            for (int ii = 0; ii < 8; ii++)
                #pragma unroll
                for (int jj = 0; jj < 4; jj++)
                    acc[ii][jj] += a[ii]*bb[jj];
        }
        if (pref) {
            int nb = (kt + 1) & 1;
            As[nb][ak+0][ar]=a0n.x; As[nb][ak+1][ar]=a0n.y;
            As[nb][ak+2][ar]=a0n.z; As[nb][ak+3][ar]=a0n.w;
            As[nb][ak+4][ar]=a1n.x; As[nb][ak+5][ar]=a1n.y;
            As[nb][ak+6][ar]=a1n.z; As[nb][ak+7][ar]=a1n.w;
            *(float4*)&Bs[nb][br][bc] = bn;
        }
        __syncthreads();
    }
    #pragma unroll
    for (int ii = 0; ii < 8; ii++) {
        int m = m0 + ty*8 + ii;
        int n = n0 + tx*4;
        float4 r;
        r.x = acc[ii][0]; r.y = acc[ii][1]; r.z = acc[ii][2]; r.w = acc[ii][3];
        if (bias) {
            float4 bv = *(const float4*)&bias[n];
            r.x += bv.x; r.y += bv.y; r.z += bv.z; r.w += bv.w;
        }
        if (sig) {
            r.x = 1.f/(1.f+expf(-r.x)); r.y = 1.f/(1.f+expf(-r.y));
            r.z = 1.f/(1.f+expf(-r.z)); r.w = 1.f/(1.f+expf(-r.w));
        }
        if (mulp) {
            float4 mv = *(const float4*)&mulp[(size_t)m*N + n];
            r.x *= mv.x; r.y *= mv.y; r.z *= mv.z; r.w *= mv.w;
        }
        *(float4*)&C[(size_t)m*N + n] = r;
    }
}

// ---------------- elementwise ----------------
__global__ void adaln_ew_kernel(const float* __restrict__ t1,
                                const float* __restrict__ t2,
                                const float* __restrict__ aln,
                                float* __restrict__ a2, int n)
{
    int i = blockIdx.x * blockDim.x + threadIdx.x;
    if (i < n) {
        float s = 1.f / (1.f + expf(-t1[i]));
        a2[i] = s * aln[i] + t2[i];
    }
}

// ---------------- pair bias: scores[b][h][i][j] = LN(z_ij)@Wb + beta -------
// Block: 64 j-rows for a fixed (b,i). 256 threads. No shuffles in hot loop.
__global__ void __launch_bounds__(256)
pairbias_kernel(const float* __restrict__ z,
                const float* __restrict__ beta,
                const float* __restrict__ lnb_w,
                const float* __restrict__ lnb_b,
                const float* __restrict__ Wb,
                float* __restrict__ scores)
{
    __shared__ __align__(16) float4 zt4[64][33];   // 64 rows x 128 c (pad 132 floats)
    __shared__ __align__(16) float  wb2[128][16];  // lnb_w[c]*Wb[c][h]
    __shared__ float  bt[64*16];                   // beta tile, xor-swizzled
    __shared__ float  colsum[16], consth[16];
    __shared__ float  mean_s[64], rs_s[64];
    __shared__ float  ps1[64][4], ps2[64][4];

    int t  = threadIdx.x;
    int j0 = blockIdx.x * 64;
    int bi = blockIdx.y;
    int b  = bi / II, i = bi % II;

    // stage wb2 (coalesced over Wb)
    for (int e = t; e < 128 * 16; e += 256) {
        int c = e >> 4, h = e & 15;
        wb2[c][h] = lnb_w[c] * Wb[c * 16 + h];
    }
    // stage beta tile: contiguous 4KB, xor-swizzled store for conflict-free read
    {
        const float4* bg = (const float4*)(beta + ((size_t)bi * II + j0) * HH);
        float4 v = bg[t];
        int e = t * 4;
        int j = e >> 4, h = e & 15;
        bt[j*16 + ((h+0 + j) & 15)] = v.x;
        bt[j*16 + ((h+1 + j) & 15)] = v.y;
        bt[j*16 + ((h+2 + j) & 15)] = v.z;
        bt[j*16 + ((h+3 + j) & 15)] = v.w;
    }
    // stage z tile: 64 rows x 128 c, fully contiguous 32KB
    {
        const float4* zg = (const float4*)(z + ((size_t)bi * II + j0) * CZ);
        #pragma unroll
        for (int e = t; e < 2048; e += 256) {
            int r = e >> 5, q = e & 31;
            zt4[r][q] = zg[(size_t)r * 32 + q];
        }
    }
    __syncthreads();

    // row stats partials: 4 threads per row
    {
        int srow = t >> 2, seg = t & 3;
        const float* zr = (const float*)zt4[srow];
        float s1 = 0.f, s2 = 0.f;
        #pragma unroll
        for (int u = 0; u < 32; u++) {
            float v = zr[seg * 32 + u];
            s1 += v; s2 += v * v;
        }
        ps1[srow][seg] = s1; ps2[srow][seg] = s2;
    }
    if (t < 16) {
        float cs = 0.f, ch = 0.f;
        for (int c = 0; c < 128; c++) {
            cs += wb2[c][t];
            ch += lnb_b[c] * Wb[c * 16 + t];
        }
        colsum[t] = cs; consth[t] = ch;
    }
    __syncthreads();
    if (t < 64) {
        float a  = ps1[t][0] + ps1[t][1] + ps1[t][2] + ps1[t][3];
        float b2 = ps2[t][0] + ps2[t][1] + ps2[t][2] + ps2[t][3];
        float m  = a * (1.f / 128.f);
        float var = b2 * (1.f / 128.f) - m * m;
        mean_s[t] = m;
        rs_s[t]   = rsqrtf(var + EPS);
    }

    // main: each thread owns one row, one 32-c split, all 16 heads
    int crow = t & 63, part = t >> 6;
    float acc[16] = {};
    {
        const float4* zr = zt4[crow];
        #pragma unroll
        for (int cc = 0; cc < 8; cc++) {
            int c4 = part * 8 + cc;
            float4 z4 = zr[c4];
            #pragma unroll
            for (int u = 0; u < 4; u++) {
                float zc = (u == 0) ? z4.x : (u == 1) ? z4.y : (u == 2) ? z4.z : z4.w;
                const float4* wr = (const float4*)wb2[c4 * 4 + u];
                #pragma unroll
                for (int hq = 0; hq < 4; hq++) {
                    float4 w = wr[hq];
                    acc[hq*4+0] += zc * w.x;
                    acc[hq*4+1] += zc * w.y;
                    acc[hq*4+2] += zc * w.z;
                    acc[hq*4+3] += zc * w.w;
                }
            }
        }
    }
    __syncthreads();                    // all zt reads done; alias zt as pacc
    float* pacc = (float*)zt4;          // [4][64][17]
    {
        int base = (part * 64 + crow) * 17;
        #pragma unroll
        for (int h = 0; h < 16; h++) pacc[base + h] = acc[h];
    }
    __syncthreads();

    // epilogue: combine splits, apply LN closed form + beta, write scores
    {
        int j = t & 63, hb = t >> 6;
        float mean = mean_s[j], rs = rs_s[j];
        #pragma unroll
        for (int u = 0; u < 4; u++) {
            int h = hb * 4 + u;
            float v = pacc[(0*64 + j)*17 + h] + pacc[(1*64 + j)*17 + h]
                    + pacc[(2*64 + j)*17 + h] + pacc[(3*64 + j)*17 + h];
            v = rs * (v - mean * colsum[h]) + consth[h] + bt[j*16 + ((h + j) & 15)];
            scores[(((size_t)(b*16 + h)) * II + i) * II + j0 + j] = v;
        }
    }
}

// ---------------- scores += q.k / sqrt(D) : 64x64 tile, 4x4 micro ----------
__global__ void __launch_bounds__(256)
qk_kernel(const float* __restrict__ q, const float* __restrict__ k,
          float* __restrict__ scores)
{
    __shared__ __align__(16) float qs[48][68];   // [d][i]
    __shared__ __align__(16) float ks[48][68];   // [d][j]
    int bh = blockIdx.z;
    int b = bh >> 4, h = bh & 15;
    int i0 = blockIdx.y * 64, j0 = blockIdx.x * 64;
    int t = threadIdx.x;
    for (int e = t; e < 64 * 48; e += 256) {
        int r = e / 48, d = e % 48;
        qs[d][r] = q[(((size_t)b * II + i0 + r) * HH + h) * DD + d];
        ks[d][r] = k[(((size_t)b * II + j0 + r) * HH + h) * DD + d];
    }
    __syncthreads();
    int tx = t & 15, ty = t >> 4;
    float acc[4][4] = {};
    #pragma unroll 4
    for (int d = 0; d < 48; d++) {
        float4 a4 = *(const float4*)&qs[d][ty * 4];
        float4 b4 = *(const float4*)&ks[d][tx * 4];
        float a[4] = {a4.x, a4.y, a4.z, a4.w};
        float bb[4] = {b4.x, b4.y, b4.z, b4.w};
        #pragma unroll
        for (int ii = 0; ii < 4; ii++)
            #pragma unroll
            for (int jj = 0; jj < 4; jj++)
                acc[ii][jj] += a[ii] * bb[jj];
    }
    const float sc = rsqrtf(48.f);
    #pragma unroll
    for (int ii = 0; ii < 4; ii++) {
        size_t base = (((size_t)bh * II) + i0 + ty * 4 + ii) * II + j0 + tx * 4;
        float4 old = *(float4*)&scores[base];
        old.x += acc[ii][0] * sc; old.y += acc[ii][1] * sc;
        old.z += acc[ii][2] * sc; old.w += acc[ii][3] * sc;
        *(float4*)&scores[base] = old;
    }
}

// ---------------- softmax over j + AV + gate: o[b,i,h,d] ----------------
__global__ void __launch_bounds__(192)
softmax_av_kernel(const float* __restrict__ scores,
                  const float* __restrict__ v,
                  const float* __restrict__ gbuf,
                  float* __restrict__ o)
{
    __shared__ __align__(16) float p[16][II];    // 48KB
    __shared__ __align__(16) float vt[48][36];   // [d][j] transposed, 6.75KB
    int bh = blockIdx.y, b = bh >> 4, h = bh & 15;
    int ibase = blockIdx.x * 16;
    int t = threadIdx.x, warp = t >> 5, lane = t & 31;

    // phase 1: softmax of 16 rows
    for (int r = warp; r < 16; r += 6) {
        const float* srow = &scores[(((size_t)bh * II) + ibase + r) * II];
        float mx = -1e30f;
        for (int j = lane; j < II; j += 32) {
            float s = srow[j]; p[r][j] = s; mx = fmaxf(mx, s);
        }
        #pragma unroll
        for (int off = 16; off; off >>= 1) mx = fmaxf(mx, __shfl_xor_sync(0xffffffffu, mx, off));
        float sum = 0.f;
        for (int j = lane; j < II; j += 32) {
            float e = expf(p[r][j] - mx); p[r][j] = e; sum += e;
        }
        #pragma unroll
        for (int off = 16; off; off >>= 1) sum += __shfl_xor_sync(0xffffffffu, sum, off);
        float inv = 1.f / sum;
        for (int j = lane; j < II; j += 32) p[r][j] *= inv;
    }
    __syncthreads();

    // phase 2: o[i,d] = sum_j p[i][j] * v[j][d]
    int ia = t / 24, d0 = t % 24;            // ia 0..7, d0 0..23
    float acc[2][2] = {};
    for (int jt = 0; jt < II / 32; jt++) {
        for (int e = t; e < 32 * 48; e += 192) {
            int jj = e / 48, d = e % 48;
            vt[d][jj] = v[(((size_t)b * II + jt * 32 + jj) * HH + h) * DD + d];
        }
        __syncthreads();
        #pragma unroll
        for (int jj = 0; jj < 32; jj += 4) {
            float4 p0 = *(const float4*)&p[ia][jt * 32 + jj];
            float4 p1 = *(const float4*)&p[ia + 8][jt * 32 + jj];
            float4 v0 = *(const float4*)&vt[d0][jj];
            float4 v1 = *(const float4*)&vt[d0 + 24][jj];
            acc[0][0] += p0.x*v0.x + p0.y*v0.y + p0.z*v0.z + p0.w*v0.w;
            acc[0][1] += p0.x*v1.x + p0.y*v1.y + p0.z*v1.z + p0.w*v1.w;
            acc[1][0] += p1.x*v0.x + p1.y*v0.y + p1.z*v0.z + p1.w*v0.w;
            acc[1][1] += p1.x*v1.x + p1.y*v1.y + p1.z*v1.z + p1.w*v1.w;
        }
        __syncthreads();
    }
    #pragma unroll
    for (int u = 0; u < 2; u++)
        #pragma unroll
        for (int w2 = 0; w2 < 2; w2++) {
            int i = ibase + ia + u * 8;
            int d = d0 + w2 * 24;
            size_t gi = (((size_t)b * II + i) * HH + h) * DD + d;
            float g = 1.f / (1.f + expf(-gbuf[gi]));
            o[gi] = acc[u][w2] * g;
        }
}

// ---------------- host launch ----------------
static float* sym(const void* s) {
    void* p = nullptr;
    cudaGetSymbolAddress(&p, s);
    return (float*)p;
}

extern "C" void kernel_launch(void* const* d_in, const int* in_sizes, int n_in,
                              void* d_out, int out_size)
{
    const float* a_i      = (const float*)d_in[0];
    const float* s_i      = (const float*)d_in[1];
    const float* z_ij     = (const float*)d_in[2];
    const float* beta_ij  = (const float*)d_in[3];
    const float* lns_w    = (const float*)d_in[4];
    const float* lns_b    = (const float*)d_in[5];
    const float* Ws       = (const float*)d_in[6];
    const float* bs       = (const float*)d_in[7];
    const float* Wnb      = (const float*)d_in[8];
    const float* Wq       = (const float*)d_in[9];
    const float* bq       = (const float*)d_in[10];
    const float* Wk       = (const float*)d_in[11];
    const float* Wv       = (const float*)d_in[12];
    const float* lnb_w    = (const float*)d_in[13];
    const float* lnb_b    = (const float*)d_in[14];
    const float* Wb       = (const float*)d_in[15];
    const float* Wg       = (const float*)d_in[16];
    const float* Wo       = (const float*)d_in[17];
    const float* Ws_out   = (const float*)d_in[18];
    const float* bs_out   = (const float*)d_in[19];
    float* out = (float*)d_out;

    float* p_aln  = sym(g_aln);
    float* p_sln  = sym(g_sln);
    float* p_t1   = sym(g_t1);
    float* p_t2   = sym(g_t2);
    float* p_a2   = sym(g_a2);
    float* p_q    = sym(g_q);
    float* p_k    = sym(g_k);
    float* p_v    = sym(g_v);
    float* p_g    = sym(g_gbuf);
    float* p_gate = sym(g_gate);
    float* p_sc   = sym(g_scores);
    float* p_o    = sym(g_o);

    const int NEL = ROWS * CA;

    // pair bias first (independent of everything else)
    {
        dim3 g(II / 64, ROWS);
        pairbias_kernel<<<g, 256>>>(z_ij, beta_ij, lnb_w, lnb_b, Wb, p_sc);
    }

    // LayerNorms
    ln_kernel<<<ROWS, 256>>>(a_i, nullptr, nullptr, p_aln, CA);
    ln_kernel<<<ROWS, 256>>>(s_i, lns_w, lns_b, p_sln, CS);

    // AdaLN
    {
        dim3 g(CA / 64, ROWS / 128);
        gemm_kernel<<<g, 256>>>(p_sln, Ws,  bs,      nullptr, p_t1, ROWS, CA, CS, 0);
        gemm_kernel<<<g, 256>>>(p_sln, Wnb, nullptr, nullptr, p_t2, ROWS, CA, CS, 0);
    }
    adaln_ew_kernel<<<(NEL + 255) / 256, 256>>>(p_t1, p_t2, p_aln, p_a2, NEL);

    // projections
    {
        dim3 g(HC / 64, ROWS / 128);
        gemm_kernel<<<g, 256>>>(p_a2, Wq, bq,      nullptr, p_q, ROWS, HC, CA, 0);
        gemm_kernel<<<g, 256>>>(p_a2, Wk, nullptr, nullptr, p_k, ROWS, HC, CA, 0);
        gemm_kernel<<<g, 256>>>(p_a2, Wv, nullptr, nullptr, p_v, ROWS, HC, CA, 0);
        gemm_kernel<<<g, 256>>>(p_a2, Wg, nullptr, nullptr, p_g, ROWS, HC, CA, 0);
    }

    // output gate from raw s_i
    {
        dim3 g(CA / 64, ROWS / 128);
        gemm_kernel<<<g, 256>>>(s_i, Ws_out, bs_out, nullptr, p_gate, ROWS, CA, CS, 1);
    }

    // scores += qk/sqrt(D)
    {
        dim3 g(II / 64, II / 64, BB * HH);
        qk_kernel<<<g, 256>>>(p_q, p_k, p_sc);
    }

    // softmax + AV + gate
    {
        dim3 g(II / 16, BB * HH);
        softmax_av_kernel<<<g, 192>>>(p_sc, p_v, p_g, p_o);
    }

    // out = gate * (o @ Wo)   (gating folded into GEMM epilogue)
    {
        dim3 g(CA / 64, ROWS / 128);
        gemm_kernel<<<g, 256>>>(p_o, Wo, nullptr, p_gate, out, ROWS, CA, HC, 0);
    }
}

// round 6
// speedup vs baseline: 2.9078x; 1.0950x over previous
#include <cuda_runtime.h>
#include <cuda_bf16.h>
#include <math.h>

// Problem constants
#define BB 2
#define II 768
#define CA 768
#define CS 384
#define CZ 128
#define HH 16
#define DD 48
#define HC 768
#define ROWS (BB*II)          // 1536
#define EPS 1e-5f

// ---------------- device scratch (no allocations allowed) ----------------
__device__ float g_aln  [ROWS*CA];
__device__ float g_sln  [ROWS*CS];
__device__ float g_t1   [ROWS*CA];
__device__ float g_t2   [ROWS*CA];
__device__ float g_a2   [ROWS*CA];
__device__ float g_q    [ROWS*HC];
__device__ float g_k    [ROWS*HC];
__device__ float g_v    [ROWS*HC];
__device__ float g_gbuf [ROWS*HC];
__device__ float g_gate [ROWS*CA];
__device__ float g_scores[(size_t)BB*HH*II*II];   // [b][h][i][j]  ~75.5 MB
__device__ float g_o    [ROWS*HC];

// ---------------- tf32 helpers ----------------
__device__ __forceinline__ unsigned f2tf(float x) {
    unsigned u;
    asm("cvt.rna.tf32.f32 %0, %1;" : "=r"(u) : "f"(x));
    return u;
}

__device__ __forceinline__ void mma_tf32(float* d, const unsigned* a, const unsigned* b) {
    asm volatile(
        "mma.sync.aligned.m16n8k8.row.col.f32.tf32.tf32.f32 "
        "{%0,%1,%2,%3}, {%4,%5,%6,%7}, {%8,%9}, {%0,%1,%2,%3};"
        : "+f"(d[0]), "+f"(d[1]), "+f"(d[2]), "+f"(d[3])
        : "r"(a[0]), "r"(a[1]), "r"(a[2]), "r"(a[3]), "r"(b[0]), "r"(b[1]));
}

// One 8-deep K slice: 2 m-tiles x 4 n-tiles of m16n8k8, 3xTF32 (hi*hi + hi*lo + lo*hi)
template<int SA, int SB>
__device__ __forceinline__ void do_mma8(const float* AhP, const float* AlP,
                                        const float* BhP, const float* BlP,
                                        int kk, int wm, int wn, int l4, int g,
                                        float acc[2][4][4])
{
    unsigned ah[2][4], al[2][4], bh[4][2], bl[4][2];
    const float* r0 = AhP + (kk + l4) * SA;
    const float* r1 = AhP + (kk + l4 + 4) * SA;
    const float* s0 = AlP + (kk + l4) * SA;
    const float* s1 = AlP + (kk + l4 + 4) * SA;
    #pragma unroll
    for (int mt = 0; mt < 2; mt++) {
        int mm = wm + mt * 16;
        ah[mt][0] = __float_as_uint(r0[mm + g]);
        ah[mt][1] = __float_as_uint(r0[mm + g + 8]);
        ah[mt][2] = __float_as_uint(r1[mm + g]);
        ah[mt][3] = __float_as_uint(r1[mm + g + 8]);
        al[mt][0] = __float_as_uint(s0[mm + g]);
        al[mt][1] = __float_as_uint(s0[mm + g + 8]);
        al[mt][2] = __float_as_uint(s1[mm + g]);
        al[mt][3] = __float_as_uint(s1[mm + g + 8]);
    }
    const float* t0 = BhP + (kk + l4) * SB;
    const float* t1 = BhP + (kk + l4 + 4) * SB;
    const float* u0 = BlP + (kk + l4) * SB;
    const float* u1 = BlP + (kk + l4 + 4) * SB;
    #pragma unroll
    for (int nt = 0; nt < 4; nt++) {
        int nn = wn + nt * 8 + g;
        bh[nt][0] = __float_as_uint(t0[nn]);
        bh[nt][1] = __float_as_uint(t1[nn]);
        bl[nt][0] = __float_as_uint(u0[nn]);
        bl[nt][1] = __float_as_uint(u1[nn]);
    }
    #pragma unroll
    for (int mt = 0; mt < 2; mt++)
        #pragma unroll
        for (int nt = 0; nt < 4; nt++) {
            mma_tf32(acc[mt][nt], ah[mt], bh[nt]);
            mma_tf32(acc[mt][nt], ah[mt], bl[nt]);
            mma_tf32(acc[mt][nt], al[mt], bh[nt]);
        }
}

// ---------------- LayerNorm over rows ----------------
__global__ void ln_kernel(const float* __restrict__ x,
                          const float* __restrict__ w,
                          const float* __restrict__ b,
                          float* __restrict__ y, int C)
{
    int row = blockIdx.x;
    const float* xr = x + (size_t)row * C;
    float s1 = 0.f, s2 = 0.f;
    for (int c = threadIdx.x; c < C; c += blockDim.x) {
        float v = xr[c]; s1 += v; s2 += v * v;
    }
    __shared__ float red[64];
    #pragma unroll
    for (int o = 16; o; o >>= 1) {
        s1 += __shfl_xor_sync(0xffffffffu, s1, o);
        s2 += __shfl_xor_sync(0xffffffffu, s2, o);
    }
    int wid = threadIdx.x >> 5, lid = threadIdx.x & 31;
    if (lid == 0) { red[wid] = s1; red[wid + 32] = s2; }
    __syncthreads();
    if (wid == 0) {
        s1 = (lid < (blockDim.x >> 5)) ? red[lid] : 0.f;
        s2 = (lid < (blockDim.x >> 5)) ? red[lid + 32] : 0.f;
        #pragma unroll
        for (int o = 16; o; o >>= 1) {
            s1 += __shfl_xor_sync(0xffffffffu, s1, o);
            s2 += __shfl_xor_sync(0xffffffffu, s2, o);
        }
        if (lid == 0) { red[0] = s1; red[1] = s2; }
    }
    __syncthreads();
    float mean = red[0] / C;
    float var  = red[1] / C - mean * mean;
    float rs   = rsqrtf(var + EPS);
    float* yr = y + (size_t)row * C;
    for (int c = threadIdx.x; c < C; c += blockDim.x) {
        float v = (xr[c] - mean) * rs;
        if (w) v = v * w[c] + b[c];
        yr[c] = v;
    }
}

// ---------------- tf32 tensor-core GEMM, batched over blockIdx.z ----------
struct GemmJob { const float* W; const float* bias; const float* mul; float* out; int sig; };
struct GemmBatch { GemmJob j[4]; };

// C = A[M,K] @ W[K,N]; tile 128x64, 256 threads (8 warps, 4x2), warp tile 32x32.
__global__ void __launch_bounds__(256)
gemm_tc_kernel(const float* __restrict__ A, GemmBatch batch, int M, int N, int K)
{
    __shared__ float Ah[16][136], Al[16][136];
    __shared__ float Bh[16][72],  Bl[16][72];

    GemmJob jb = batch.j[blockIdx.z];
    const float* __restrict__ W = jb.W;

    int t = threadIdx.x;
    int m0 = blockIdx.y * 128, n0 = blockIdx.x * 64;
    int w = t >> 5, lane = t & 31;
    int wm = (w >> 1) * 32, wn = (w & 1) * 32;
    int l4 = lane & 3, g = lane >> 2;

    int am = t >> 1, ak = (t & 1) * 8;
    int bk = t >> 4, bn = (t & 15) * 4;
    const float* Ap = A + (size_t)(m0 + am) * K + ak;
    const float* Wp = W + (size_t)bk * N + n0 + bn;

    float acc[2][4][4] = {};
    int nkt = K >> 4;

    float4 a0 = *(const float4*)Ap;
    float4 a1 = *(const float4*)(Ap + 4);
    float4 b0 = *(const float4*)Wp;

    for (int kt = 0; kt < nkt; kt++) {
        {   // hi/lo split + store current tile
            float av[8] = {a0.x,a0.y,a0.z,a0.w,a1.x,a1.y,a1.z,a1.w};
            #pragma unroll
            for (int u = 0; u < 8; u++) {
                float hi = __uint_as_float(f2tf(av[u]));
                Ah[ak + u][am] = hi;
                Al[ak + u][am] = __uint_as_float(f2tf(av[u] - hi));
            }
            float bv[4] = {b0.x, b0.y, b0.z, b0.w};
            float4 bhi, blo;
            float h0 = __uint_as_float(f2tf(bv[0]));
            float h1 = __uint_as_float(f2tf(bv[1]));
            float h2 = __uint_as_float(f2tf(bv[2]));
            float h3 = __uint_as_float(f2tf(bv[3]));
            bhi = make_float4(h0, h1, h2, h3);
            blo = make_float4(__uint_as_float(f2tf(bv[0]-h0)), __uint_as_float(f2tf(bv[1]-h1)),
                              __uint_as_float(f2tf(bv[2]-h2)), __uint_as_float(f2tf(bv[3]-h3)));
            *(float4*)&Bh[bk][bn] = bhi;
            *(float4*)&Bl[bk][bn] = blo;
        }
        __syncthreads();
        // prefetch next tile (overlaps mma)
        if (kt + 1 < nkt) {
            const float* Ap2 = Ap + (size_t)(kt + 1) * 16;
            a0 = *(const float4*)Ap2;
            a1 = *(const float4*)(Ap2 + 4);
            b0 = *(const float4*)(Wp + (size_t)(kt + 1) * 16 * N);
        }
        do_mma8<136, 72>(&Ah[0][0], &Al[0][0], &Bh[0][0], &Bl[0][0], 0, wm, wn, l4, g, acc);
        do_mma8<136, 72>(&Ah[0][0], &Al[0][0], &Bh[0][0], &Bl[0][0], 8, wm, wn, l4, g, acc);
        __syncthreads();
    }

    // epilogue
    const float* bias = jb.bias;
    const float* mul  = jb.mul;
    float* out = jb.out;
    int sig = jb.sig;
    #pragma unroll
    for (int mt = 0; mt < 2; mt++)
        #pragma unroll
        for (int nt = 0; nt < 4; nt++) {
            int n = n0 + wn + nt * 8 + l4 * 2;
            float bx = 0.f, by = 0.f;
            if (bias) { bx = bias[n]; by = bias[n + 1]; }
            #pragma unroll
            for (int half = 0; half < 2; half++) {
                int m = m0 + wm + mt * 16 + g + half * 8;
                float x = acc[mt][nt][half * 2]     + bx;
                float y = acc[mt][nt][half * 2 + 1] + by;
                if (sig) {
                    x = 1.f / (1.f + expf(-x));
                    y = 1.f / (1.f + expf(-y));
                }
                if (mul) {
                    float2 mv = *(const float2*)&mul[(size_t)m * N + n];
                    x *= mv.x; y *= mv.y;
                }
                *(float2*)&out[(size_t)m * N + n] = make_float2(x, y);
            }
        }
}

// ---------------- elementwise ----------------
__global__ void adaln_ew_kernel(const float* __restrict__ t1,
                                const float* __restrict__ t2,
                                const float* __restrict__ aln,
                                float* __restrict__ a2, int n)
{
    int i = blockIdx.x * blockDim.x + threadIdx.x;
    if (i < n) {
        float s = 1.f / (1.f + expf(-t1[i]));
        a2[i] = s * aln[i] + t2[i];
    }
}

// ---------------- pair bias: scores[b][h][i][j] = LN(z_ij)@Wb + beta -------
__global__ void __launch_bounds__(256)
pairbias_kernel(const float* __restrict__ z,
                const float* __restrict__ beta,
                const float* __restrict__ lnb_w,
                const float* __restrict__ lnb_b,
                const float* __restrict__ Wb,
                float* __restrict__ scores)
{
    __shared__ __align__(16) float4 zt4[64][33];   // 64 rows x 128 c (pad 132 floats)
    __shared__ __align__(16) float  wb2[128][16];  // lnb_w[c]*Wb[c][h]
    __shared__ float  bt[64*16];                   // beta tile, xor-swizzled
    __shared__ float  colsum[16], consth[16];
    __shared__ float  mean_s[64], rs_s[64];
    __shared__ float  ps1[64][4], ps2[64][4];

    int t  = threadIdx.x;
    int j0 = blockIdx.x * 64;
    int bi = blockIdx.y;
    int b  = bi / II, i = bi % II;

    for (int e = t; e < 128 * 16; e += 256) {
        int c = e >> 4, h = e & 15;
        wb2[c][h] = lnb_w[c] * Wb[c * 16 + h];
    }
    {
        const float4* bg = (const float4*)(beta + ((size_t)bi * II + j0) * HH);
        float4 v = bg[t];
        int e = t * 4;
        int j = e >> 4, h = e & 15;
        bt[j*16 + ((h+0 + j) & 15)] = v.x;
        bt[j*16 + ((h+1 + j) & 15)] = v.y;
        bt[j*16 + ((h+2 + j) & 15)] = v.z;
        bt[j*16 + ((h+3 + j) & 15)] = v.w;
    }
    {
        const float4* zg = (const float4*)(z + ((size_t)bi * II + j0) * CZ);
        #pragma unroll
        for (int e = t; e < 2048; e += 256) {
            int r = e >> 5, q = e & 31;
            zt4[r][q] = zg[(size_t)r * 32 + q];
        }
    }
    __syncthreads();

    {
        int srow = t >> 2, seg = t & 3;
        const float* zr = (const float*)zt4[srow];
        float s1 = 0.f, s2 = 0.f;
        #pragma unroll
        for (int u = 0; u < 32; u++) {
            float v = zr[seg * 32 + u];
            s1 += v; s2 += v * v;
        }
        ps1[srow][seg] = s1; ps2[srow][seg] = s2;
    }
    if (t < 16) {
        float cs = 0.f, ch = 0.f;
        for (int c = 0; c < 128; c++) {
            cs += wb2[c][t];
            ch += lnb_b[c] * Wb[c * 16 + t];
        }
        colsum[t] = cs; consth[t] = ch;
    }
    __syncthreads();
    if (t < 64) {
        float a  = ps1[t][0] + ps1[t][1] + ps1[t][2] + ps1[t][3];
        float b2 = ps2[t][0] + ps2[t][1] + ps2[t][2] + ps2[t][3];
        float m  = a * (1.f / 128.f);
        float var = b2 * (1.f / 128.f) - m * m;
        mean_s[t] = m;
        rs_s[t]   = rsqrtf(var + EPS);
    }

    int crow = t & 63, part = t >> 6;
    float acc[16] = {};
    {
        const float4* zr = zt4[crow];
        #pragma unroll
        for (int cc = 0; cc < 8; cc++) {
            int c4 = part * 8 + cc;
            float4 z4 = zr[c4];
            #pragma unroll
            for (int u = 0; u < 4; u++) {
                float zc = (u == 0) ? z4.x : (u == 1) ? z4.y : (u == 2) ? z4.z : z4.w;
                const float4* wr = (const float4*)wb2[c4 * 4 + u];
                #pragma unroll
                for (int hq = 0; hq < 4; hq++) {
                    float4 w = wr[hq];
                    acc[hq*4+0] += zc * w.x;
                    acc[hq*4+1] += zc * w.y;
                    acc[hq*4+2] += zc * w.z;
                    acc[hq*4+3] += zc * w.w;
                }
            }
        }
    }
    __syncthreads();
    float* pacc = (float*)zt4;          // [4][64][17]
    {
        int base = (part * 64 + crow) * 17;
        #pragma unroll
        for (int h = 0; h < 16; h++) pacc[base + h] = acc[h];
    }
    __syncthreads();

    {
        int j = t & 63, hb = t >> 6;
        float mean = mean_s[j], rs = rs_s[j];
        #pragma unroll
        for (int u = 0; u < 4; u++) {
            int h = hb * 4 + u;
            float v = pacc[(0*64 + j)*17 + h] + pacc[(1*64 + j)*17 + h]
                    + pacc[(2*64 + j)*17 + h] + pacc[(3*64 + j)*17 + h];
            v = rs * (v - mean * colsum[h]) + consth[h] + bt[j*16 + ((h + j) & 15)];
            scores[(((size_t)(b*16 + h)) * II + i) * II + j0 + j] = v;
        }
    }
}

// ---------------- scores += q.k/sqrt(D), tf32 tensor-core ------------------
// Block: 128 threads (4 warps, 2x2), 64x64 tile, K=48 in two 24-wide phases.
__global__ void __launch_bounds__(128)
qk_tc_kernel(const float* __restrict__ q, const float* __restrict__ k,
             float* __restrict__ scores)
{
    __shared__ float Qh[24][72], Ql[24][72], Kh[24][72], Kl[24][72];
    int bh = blockIdx.z, b = bh >> 4, h = bh & 15;
    int i0 = blockIdx.y * 64, j0 = blockIdx.x * 64;
    int t = threadIdx.x, w = t >> 5, lane = t & 31;
    int wm = (w >> 1) * 32, wn = (w & 1) * 32;
    int l4 = lane & 3, g = lane >> 2;

    float acc[2][4][4] = {};

    #pragma unroll
    for (int ph = 0; ph < 2; ph++) {
        {
            int row = t & 63, which = t >> 6;
            const float* src = (which ? k : q)
                + (((size_t)b * II + (which ? j0 : i0) + row) * HH + h) * DD + ph * 24;
            float (*Sh)[72] = which ? Kh : Qh;
            float (*Sl)[72] = which ? Kl : Ql;
            #pragma unroll
            for (int u = 0; u < 24; u += 4) {
                float4 v = *(const float4*)(src + u);
                float vv[4] = {v.x, v.y, v.z, v.w};
                #pragma unroll
                for (int c = 0; c < 4; c++) {
                    float hi = __uint_as_float(f2tf(vv[c]));
                    Sh[u + c][row] = hi;
                    Sl[u + c][row] = __uint_as_float(f2tf(vv[c] - hi));
                }
            }
        }
        __syncthreads();
        do_mma8<72, 72>(&Qh[0][0], &Ql[0][0], &Kh[0][0], &Kl[0][0], 0,  wm, wn, l4, g, acc);
        do_mma8<72, 72>(&Qh[0][0], &Ql[0][0], &Kh[0][0], &Kl[0][0], 8,  wm, wn, l4, g, acc);
        do_mma8<72, 72>(&Qh[0][0], &Ql[0][0], &Kh[0][0], &Kl[0][0], 16, wm, wn, l4, g, acc);
        __syncthreads();
    }

    const float sc = rsqrtf(48.f);
    #pragma unroll
    for (int mt = 0; mt < 2; mt++)
        #pragma unroll
        for (int nt = 0; nt < 4; nt++)
            #pragma unroll
            for (int half = 0; half < 2; half++) {
                int i = i0 + wm + mt * 16 + g + half * 8;
                int jj = j0 + wn + nt * 8 + l4 * 2;
                size_t idx = ((size_t)bh * II + i) * II + jj;
                float2 old = *(float2*)&scores[idx];
                old.x += acc[mt][nt][half * 2]     * sc;
                old.y += acc[mt][nt][half * 2 + 1] * sc;
                *(float2*)&scores[idx] = old;
            }
}

// ---------------- softmax over j + AV + gate: o[b,i,h,d] ----------------
__global__ void __launch_bounds__(192)
softmax_av_kernel(const float* __restrict__ scores,
                  const float* __restrict__ v,
                  const float* __restrict__ gbuf,
                  float* __restrict__ o)
{
    __shared__ __align__(16) float p[16][II];    // 48KB
    __shared__ __align__(16) float vt[48][36];   // [d][j] transposed
    int bh = blockIdx.y, b = bh >> 4, h = bh & 15;
    int ibase = blockIdx.x * 16;
    int t = threadIdx.x, warp = t >> 5, lane = t & 31;

    for (int r = warp; r < 16; r += 6) {
        const float* srow = &scores[(((size_t)bh * II) + ibase + r) * II];
        float mx = -1e30f;
        for (int j = lane; j < II; j += 32) {
            float s = srow[j]; p[r][j] = s; mx = fmaxf(mx, s);
        }
        #pragma unroll
        for (int off = 16; off; off >>= 1) mx = fmaxf(mx, __shfl_xor_sync(0xffffffffu, mx, off));
        float sum = 0.f;
        for (int j = lane; j < II; j += 32) {
            float e = expf(p[r][j] - mx); p[r][j] = e; sum += e;
        }
        #pragma unroll
        for (int off = 16; off; off >>= 1) sum += __shfl_xor_sync(0xffffffffu, sum, off);
        float inv = 1.f / sum;
        for (int j = lane; j < II; j += 32) p[r][j] *= inv;
    }
    __syncthreads();

    int ia = t / 24, d0 = t % 24;
    float acc[2][2] = {};
    for (int jt = 0; jt < II / 32; jt++) {
        for (int e = t; e < 32 * 48; e += 192) {
            int jj = e / 48, d = e % 48;
            vt[d][jj] = v[(((size_t)b * II + jt * 32 + jj) * HH + h) * DD + d];
        }
        __syncthreads();
        #pragma unroll
        for (int jj = 0; jj < 32; jj += 4) {
            float4 p0 = *(const float4*)&p[ia][jt * 32 + jj];
            float4 p1 = *(const float4*)&p[ia + 8][jt * 32 + jj];
            float4 v0 = *(const float4*)&vt[d0][jj];
            float4 v1 = *(const float4*)&vt[d0 + 24][jj];
            acc[0][0] += p0.x*v0.x + p0.y*v0.y + p0.z*v0.z + p0.w*v0.w;
            acc[0][1] += p0.x*v1.x + p0.y*v1.y + p0.z*v1.z + p0.w*v1.w;
            acc[1][0] += p1.x*v0.x + p1.y*v0.y + p1.z*v0.z + p1.w*v0.w;
            acc[1][1] += p1.x*v1.x + p1.y*v1.y + p1.z*v1.z + p1.w*v1.w;
        }
        __syncthreads();
    }
    #pragma unroll
    for (int u = 0; u < 2; u++)
        #pragma unroll
        for (int w2 = 0; w2 < 2; w2++) {
            int i = ibase + ia + u * 8;
            int d = d0 + w2 * 24;
            size_t gi = (((size_t)b * II + i) * HH + h) * DD + d;
            float g = 1.f / (1.f + expf(-gbuf[gi]));
            o[gi] = acc[u][w2] * g;
        }
}

// ---------------- host launch ----------------
static float* sym(const void* s) {
    void* p = nullptr;
    cudaGetSymbolAddress(&p, s);
    return (float*)p;
}

extern "C" void kernel_launch(void* const* d_in, const int* in_sizes, int n_in,
                              void* d_out, int out_size)
{
    const float* a_i      = (const float*)d_in[0];
    const float* s_i      = (const float*)d_in[1];
    const float* z_ij     = (const float*)d_in[2];
    const float* beta_ij  = (const float*)d_in[3];
    const float* lns_w    = (const float*)d_in[4];
    const float* lns_b    = (const float*)d_in[5];
    const float* Ws       = (const float*)d_in[6];
    const float* bs       = (const float*)d_in[7];
    const float* Wnb      = (const float*)d_in[8];
    const float* Wq       = (const float*)d_in[9];
    const float* bq       = (const float*)d_in[10];
    const float* Wk       = (const float*)d_in[11];
    const float* Wv       = (const float*)d_in[12];
    const float* lnb_w    = (const float*)d_in[13];
    const float* lnb_b    = (const float*)d_in[14];
    const float* Wb       = (const float*)d_in[15];
    const float* Wg       = (const float*)d_in[16];
    const float* Wo       = (const float*)d_in[17];
    const float* Ws_out   = (const float*)d_in[18];
    const float* bs_out   = (const float*)d_in[19];
    float* out = (float*)d_out;

    float* p_aln  = sym(g_aln);
    float* p_sln  = sym(g_sln);
    float* p_t1   = sym(g_t1);
    float* p_t2   = sym(g_t2);
    float* p_a2   = sym(g_a2);
    float* p_q    = sym(g_q);
    float* p_k    = sym(g_k);
    float* p_v    = sym(g_v);
    float* p_g    = sym(g_gbuf);
    float* p_gate = sym(g_gate);
    float* p_sc   = sym(g_scores);
    float* p_o    = sym(g_o);

    const int NEL = ROWS * CA;

    // pair bias first (independent of everything else)
    {
        dim3 g(II / 64, ROWS);
        pairbias_kernel<<<g, 256>>>(z_ij, beta_ij, lnb_w, lnb_b, Wb, p_sc);
    }

    // LayerNorms
    ln_kernel<<<ROWS, 256>>>(a_i, nullptr, nullptr, p_aln, CA);
    ln_kernel<<<ROWS, 256>>>(s_i, lns_w, lns_b, p_sln, CS);

    // AdaLN: t1 = sln@Ws + bs ; t2 = sln@Wnb   (fused in z)
    {
        GemmBatch gb = {};
        gb.j[0] = { Ws,  bs,      nullptr, p_t1, 0 };
        gb.j[1] = { Wnb, nullptr, nullptr, p_t2, 0 };
        dim3 g(CA / 64, ROWS / 128, 2);
        gemm_tc_kernel<<<g, 256>>>(p_sln, gb, ROWS, CA, CS);
    }
    adaln_ew_kernel<<<(NEL + 255) / 256, 256>>>(p_t1, p_t2, p_aln, p_a2, NEL);

    // projections q,k,v,g  (fused in z)
    {
        GemmBatch gb = {};
        gb.j[0] = { Wq, bq,      nullptr, p_q, 0 };
        gb.j[1] = { Wk, nullptr, nullptr, p_k, 0 };
        gb.j[2] = { Wv, nullptr, nullptr, p_v, 0 };
        gb.j[3] = { Wg, nullptr, nullptr, p_g, 0 };
        dim3 g(HC / 64, ROWS / 128, 4);
        gemm_tc_kernel<<<g, 256>>>(p_a2, gb, ROWS, HC, CA);
    }

    // output gate from raw s_i (sigmoid)
    {
        GemmBatch gb = {};
        gb.j[0] = { Ws_out, bs_out, nullptr, p_gate, 1 };
        dim3 g(CA / 64, ROWS / 128, 1);
        gemm_tc_kernel<<<g, 256>>>(s_i, gb, ROWS, CA, CS);
    }

    // scores += qk/sqrt(D)
    {
        dim3 g(II / 64, II / 64, BB * HH);
        qk_tc_kernel<<<g, 128>>>(p_q, p_k, p_sc);
    }

    // softmax + AV + gate
    {
        dim3 g(II / 16, BB * HH);
        softmax_av_kernel<<<g, 192>>>(p_sc, p_v, p_g, p_o);
    }

    // out = gate * (o @ Wo)
    {
        GemmBatch gb = {};
        gb.j[0] = { Wo, nullptr, p_gate, out, 0 };
        dim3 g(CA / 64, ROWS / 128, 1);
        gemm_tc_kernel<<<g, 256>>>(p_o, gb, ROWS, CA, HC);
    }
}